// round 10
// baseline (speedup 1.0000x reference)
#include <cuda_runtime.h>
#include <cmath>

// ---------------- problem constants ----------------
#define LT   128            // time dim (attention "batch")
#define SQ   512            // sequence dim (original batch B)
#define HH   8
#define DD   4
#define DM   32
#define UU   35             // top-k / sample count
#define CC   32
#define KF   4096           // C*L  (FFN inner dim A)
#define NH   8192           // FFN hidden dim
#define LH   (LT*HH)        // 1024

// ---------------- scratch (device globals; allocation-free) ----------------
__device__ __align__(16) float g_Q[LH*SQ*DD];
__device__ __align__(16) float g_K[LH*SQ*DD];
__device__ __align__(16) float g_V[LH*SQ*DD];
__device__ __align__(16) float g_ctx[LH*SQ*DD];
__device__ float g_M[LH*SQ];
__device__ int   g_Mtop[LH*UU];
__device__ __align__(16) float g_upd[LH*UU*DD];
__device__ int   g_sidx[SQ*UU];
__device__ __align__(16) float g_xh[SQ*KF];       // BN1 output == FFN input (B, C*L)
__device__ __align__(16) float g_hidden[SQ*NH];   // FFN hidden (B, 8192)

// ---------------- packed f32x2 helpers (Blackwell FFMA2 path) ---------------
__device__ __forceinline__ unsigned long long pack2_dup(float v) {
    unsigned long long r;
    unsigned int b = __float_as_uint(v);
    asm("mov.b64 %0, {%1, %1};" : "=l"(r) : "r"(b));
    return r;
}
__device__ __forceinline__ void ffma2(unsigned long long& d,
                                      unsigned long long a, unsigned long long b) {
    asm("fma.rn.f32x2 %0, %1, %2, %0;" : "+l"(d) : "l"(a), "l"(b));
}
__device__ __forceinline__ float2 unpack2(unsigned long long v) {
    unsigned int lo, hi;
    asm("mov.b64 {%0, %1}, %2;" : "=r"(lo), "=r"(hi) : "l"(v));
    return make_float2(__uint_as_float(lo), __uint_as_float(hi));
}

// ---------------- 0: index dtype normalize (int64 or int32 -> int32) --------
__global__ void k_idx(const int* __restrict__ raw) {
    bool is64 = true;
#pragma unroll
    for (int i = 1; i < 128; i += 2)
        if (raw[i] != 0) is64 = false;     // int64 little-endian high words are 0
    int t = blockIdx.x * blockDim.x + threadIdx.x;
    if (t < SQ * UU) g_sidx[t] = is64 ? raw[2 * t] : raw[t];
}

// ---------------- 1: QKV projection ----------------------------------------
// x: (B=512, C=32, L=128).  xa[l][b][c] = x[b][c][l].
// Q/K/V layout: [l][h][s=b][d], contiguous float4 per (l,h,s).
__global__ void k_qkv(const float* __restrict__ x,
                      const float* __restrict__ Wq, const float* __restrict__ bq,
                      const float* __restrict__ Wk, const float* __restrict__ bk,
                      const float* __restrict__ Wv, const float* __restrict__ bv)
{
    __shared__ float sW[3 * DM * DM];
    __shared__ float sb[3 * DM];
    int l = threadIdx.x;   // 0..127
    int b = blockIdx.x;    // 0..511
    for (int i = l; i < DM * DM; i += LT) {
        sW[i] = Wq[i]; sW[DM*DM + i] = Wk[i]; sW[2*DM*DM + i] = Wv[i];
    }
    if (l < DM) { sb[l] = bq[l]; sb[DM + l] = bk[l]; sb[2*DM + l] = bv[l]; }
    __syncthreads();

    float xr[DM];
#pragma unroll
    for (int c = 0; c < DM; c++) xr[c] = x[(b * CC + c) * LT + l];

    for (int m = 0; m < DM; m++) {
        float aq = sb[m], ak = sb[DM + m], av = sb[2*DM + m];
#pragma unroll
        for (int c = 0; c < DM; c++) {
            float xv = xr[c];
            aq = fmaf(sW[m*DM + c],          xv, aq);
            ak = fmaf(sW[DM*DM + m*DM + c],  xv, ak);
            av = fmaf(sW[2*DM*DM + m*DM + c],xv, av);
        }
        int h = m >> 2, d = m & 3;
        int o = ((l * HH + h) * SQ + b) * DD + d;
        g_Q[o] = aq; g_K[o] = ak; g_V[o] = av;
    }
}

// ---------------- 2: sampled QK -> M = max - mean ---------------------------
__global__ void k_sampleM() {
    __shared__ float4 Ksh[SQ];
    int lh = blockIdx.x;
    int s  = threadIdx.x;  // 0..511
    Ksh[s] = ((const float4*)g_K)[lh * SQ + s];
    __syncthreads();
    float4 q = ((const float4*)g_Q)[lh * SQ + s];
    float mx = -1e30f, sm = 0.f;
    const int* ip = &g_sidx[s * UU];
#pragma unroll 5
    for (int j = 0; j < UU; j++) {
        float4 k = Ksh[ip[j]];
        float d = q.x*k.x + q.y*k.y + q.z*k.z + q.w*k.w;
        mx = fmaxf(mx, d); sm += d;
    }
    g_M[lh * SQ + s] = mx - sm * (1.0f / SQ);
}

// ---------------- 3: top-35 (value desc, index asc on ties, like lax.top_k) -
__global__ void k_topk() {
    __shared__ float sv[SQ];
    __shared__ float rv[SQ];
    __shared__ int   ri[SQ];
    __shared__ int   swin;
    int lh = blockIdx.x, s = threadIdx.x;
    sv[s] = g_M[lh * SQ + s];
    __syncthreads();
    for (int it = 0; it < UU; it++) {
        rv[s] = sv[s]; ri[s] = s;
        __syncthreads();
        for (int off = SQ / 2; off > 0; off >>= 1) {
            if (s < off) {
                float v2 = rv[s + off]; int i2 = ri[s + off];
                if (v2 > rv[s] || (v2 == rv[s] && i2 < ri[s])) { rv[s] = v2; ri[s] = i2; }
            }
            __syncthreads();
        }
        if (s == 0) { g_Mtop[lh * UU + it] = ri[0]; swin = ri[0]; }
        __syncthreads();
        if (s == swin) sv[s] = -1e30f;
        __syncthreads();
    }
}

// ---------------- 4: sparse causal attention -> upd -------------------------
__global__ void k_attn() {
    __shared__ float4 Ksh[SQ];
    __shared__ float4 Vsh[SQ];
    int lh = blockIdx.x;
    int tid = threadIdx.x;          // 256
    const float4* Kp = (const float4*)g_K + lh * SQ;
    const float4* Vp = (const float4*)g_V + lh * SQ;
    for (int i = tid; i < SQ; i += 256) { Ksh[i] = Kp[i]; Vsh[i] = Vp[i]; }
    __syncthreads();
    int w = tid >> 5, lane = tid & 31;
    for (int u = w; u < UU; u += 8) {
        int su = g_Mtop[lh * UU + u];
        float4 q = ((const float4*)g_Q)[lh * SQ + su];
        q.x *= 0.5f; q.y *= 0.5f; q.z *= 0.5f; q.w *= 0.5f;   // 1/sqrt(D)
        int nk = su + 1;                                       // causal: k <= su
        float mx = -1e30f;
        for (int k = lane; k < nk; k += 32) {
            float4 kv = Ksh[k];
            mx = fmaxf(mx, q.x*kv.x + q.y*kv.y + q.z*kv.z + q.w*kv.w);
        }
#pragma unroll
        for (int o = 16; o > 0; o >>= 1) mx = fmaxf(mx, __shfl_xor_sync(0xffffffffu, mx, o));
        float sum = 0.f, ax = 0.f, ay = 0.f, az = 0.f, aw = 0.f;
        for (int k = lane; k < nk; k += 32) {
            float4 kv = Ksh[k];
            float d = q.x*kv.x + q.y*kv.y + q.z*kv.z + q.w*kv.w;
            float e = expf(d - mx);
            float4 vv = Vsh[k];
            sum += e; ax += e*vv.x; ay += e*vv.y; az += e*vv.z; aw += e*vv.w;
        }
#pragma unroll
        for (int o = 16; o > 0; o >>= 1) {
            sum += __shfl_xor_sync(0xffffffffu, sum, o);
            ax  += __shfl_xor_sync(0xffffffffu, ax,  o);
            ay  += __shfl_xor_sync(0xffffffffu, ay,  o);
            az  += __shfl_xor_sync(0xffffffffu, az,  o);
            aw  += __shfl_xor_sync(0xffffffffu, aw,  o);
        }
        if (lane == 0) {
            float inv = 1.0f / sum;
            ((float4*)g_upd)[lh * UU + u] = make_float4(ax*inv, ay*inv, az*inv, aw*inv);
        }
    }
}

// ---------------- 5: cumsum(V) + scatter upd -> ctx -------------------------
__global__ void k_ctx() {
    __shared__ float4 buf[SQ];
    int lh = blockIdx.x, s = threadIdx.x;
    buf[s] = ((const float4*)g_V)[lh * SQ + s];
    __syncthreads();
    for (int off = 1; off < SQ; off <<= 1) {
        float4 a = buf[s];
        float4 b = make_float4(0.f, 0.f, 0.f, 0.f);
        if (s >= off) b = buf[s - off];
        __syncthreads();
        a.x += b.x; a.y += b.y; a.z += b.z; a.w += b.w;
        buf[s] = a;
        __syncthreads();
    }
    if (s < UU) {
        int su = g_Mtop[lh * UU + s];
        buf[su] = ((const float4*)g_upd)[lh * UU + s];
    }
    __syncthreads();
    ((float4*)g_ctx)[lh * SQ + s] = buf[s];
}

// ---------------- 6: Wo projection + relu + residual + BN1 -> xh ------------
__global__ void k_out1(const float* __restrict__ x,
                       const float* __restrict__ Wo, const float* __restrict__ bo,
                       const float* __restrict__ g1, const float* __restrict__ be1,
                       const float* __restrict__ mu1, const float* __restrict__ va1)
{
    __shared__ float sW[DM * DM];
    __shared__ float sbo[DM], ssc[DM], ssh[DM];
    int l = threadIdx.x, b = blockIdx.x;
    for (int i = l; i < DM * DM; i += LT) sW[i] = Wo[i];
    if (l < DM) {
        sbo[l] = bo[l];
        float sc = g1[l] * rsqrtf(va1[l] + 1e-5f);
        ssc[l] = sc; ssh[l] = be1[l] - mu1[l] * sc;
    }
    __syncthreads();

    float cr[DM];
#pragma unroll
    for (int h = 0; h < HH; h++) {
        float4 t = ((const float4*)g_ctx)[(l * HH + h) * SQ + b];
        cr[h*4+0] = t.x; cr[h*4+1] = t.y; cr[h*4+2] = t.z; cr[h*4+3] = t.w;
    }
    for (int c = 0; c < DM; c++) {
        float a = sbo[c];
#pragma unroll
        for (int m = 0; m < DM; m++) a = fmaf(sW[c*DM + m], cr[m], a);
        a = fmaxf(a, 0.f) + x[(b * CC + c) * LT + l];
        g_xh[(b * CC + c) * LT + l] = a * ssc[c] + ssh[c];
    }
}

// ---------------- 7/8: FFN GEMMs (packed f32x2 FFMA2, fused epilogues) ------
// C[m][n] = epi( sum_k A[m][k] * W[n][k] + bias[n] )
// MODE 1: A=g_xh    (512x4096), out=g_hidden, epi = relu
// MODE 2: A=g_hidden(512x8192), out=d_out,    epi = relu + xh-residual + BN2
// Accumulators packed pairs along N: acc2[i][j] = (col 2j, col 2j+1) of the
// thread's TN columns (ordering matches the split-column Ws read).
template<int BM,int BN,int BK,int TM,int TN,int MODE>
__global__ void __launch_bounds__(256, 2)
k_gemm(const float* __restrict__ W, const float* __restrict__ bias,
       float* __restrict__ Cext, int Kdim, int Ndim,
       const float* __restrict__ g2, const float* __restrict__ be2,
       const float* __restrict__ mu2, const float* __restrict__ va2)
{
    constexpr int THREADS = (BM/TM)*(BN/TN);
    static_assert(THREADS == 256, "bad cfg");
    constexpr int AF4 = BM*BK/4/THREADS;
    constexpr int WF4 = BN*BK/4/THREADS;
    constexpr int KV  = BK/4;
    constexpr int TP  = TN/2;                 // packed pairs per row
    __shared__ __align__(16) float As[BK][BM];
    __shared__ __align__(16) float Ws[BK][BN];
    __shared__ float ssc[CC], ssh[CC];

    const float* __restrict__ A = (MODE == 1) ? g_xh : g_hidden;
    float* __restrict__ C = (MODE == 1) ? g_hidden : Cext;

    int tid = threadIdx.x;
    int tx = tid % (BN/TN);
    int ty = tid / (BN/TN);
    int m0 = blockIdx.y * BM;
    int n0 = blockIdx.x * BN;

    if (MODE == 2 && tid < CC) {
        float sc = g2[tid] * rsqrtf(va2[tid] + 1e-5f);
        ssc[tid] = sc; ssh[tid] = be2[tid] - mu2[tid] * sc;
    }

    float4 pa[AF4], pw[WF4];
#pragma unroll
    for (int p = 0; p < AF4; p++) { int f = tid + p*THREADS; int r = f/KV, c4 = f%KV;
        pa[p] = *(const float4*)(A + (size_t)(m0 + r)*Kdim + c4*4); }
#pragma unroll
    for (int p = 0; p < WF4; p++) { int f = tid + p*THREADS; int r = f/KV, c4 = f%KV;
        pw[p] = *(const float4*)(W + (size_t)(n0 + r)*Kdim + c4*4); }
#pragma unroll
    for (int p = 0; p < AF4; p++) { int f = tid + p*THREADS; int r = f/KV, c4 = f%KV;
        As[c4*4+0][r]=pa[p].x; As[c4*4+1][r]=pa[p].y; As[c4*4+2][r]=pa[p].z; As[c4*4+3][r]=pa[p].w; }
#pragma unroll
    for (int p = 0; p < WF4; p++) { int f = tid + p*THREADS; int r = f/KV, c4 = f%KV;
        Ws[c4*4+0][r]=pw[p].x; Ws[c4*4+1][r]=pw[p].y; Ws[c4*4+2][r]=pw[p].z; Ws[c4*4+3][r]=pw[p].w; }
    __syncthreads();

    unsigned long long acc2[TM][TP];
#pragma unroll
    for (int i = 0; i < TM; i++)
#pragma unroll
        for (int j = 0; j < TP; j++) acc2[i][j] = 0ull;

    int nT = Kdim / BK;
    for (int t = 0; t < nT; t++) {
        bool more = (t + 1 < nT);
        if (more) {
            int kt = (t + 1) * BK;
#pragma unroll
            for (int p = 0; p < AF4; p++) { int f = tid + p*THREADS; int r = f/KV, c4 = f%KV;
                pa[p] = *(const float4*)(A + (size_t)(m0 + r)*Kdim + kt + c4*4); }
#pragma unroll
            for (int p = 0; p < WF4; p++) { int f = tid + p*THREADS; int r = f/KV, c4 = f%KV;
                pw[p] = *(const float4*)(W + (size_t)(n0 + r)*Kdim + kt + c4*4); }
        }
#pragma unroll
        for (int kk = 0; kk < BK; kk++) {
            // A fragment: load TM floats, duplicate-pack each into f32x2
            unsigned long long arr[TM];
            {
                float4 a0 = *(const float4*)&As[kk][ty*TM];
                arr[0]=pack2_dup(a0.x); arr[1]=pack2_dup(a0.y);
                arr[2]=pack2_dup(a0.z); arr[3]=pack2_dup(a0.w);
                if constexpr (TM == 8) {
                    float4 a1 = *(const float4*)&As[kk][ty*TM + 4];
                    arr[4]=pack2_dup(a1.x); arr[5]=pack2_dup(a1.y);
                    arr[6]=pack2_dup(a1.z); arr[7]=pack2_dup(a1.w);
                }
            }
            // B fragment: adjacent column pairs read directly as 64-bit
            unsigned long long b2[TP];
            {
                const unsigned long long* w0 =
                    (const unsigned long long*)&Ws[kk][tx*4];
                b2[0] = w0[0]; b2[1] = w0[1];
                if constexpr (TN == 8) {
                    const unsigned long long* w1 =
                        (const unsigned long long*)&Ws[kk][BN/2 + tx*4];
                    b2[2] = w1[0]; b2[3] = w1[1];
                }
            }
#pragma unroll
            for (int i = 0; i < TM; i++)
#pragma unroll
                for (int j = 0; j < TP; j++)
                    ffma2(acc2[i][j], arr[i], b2[j]);
        }
        __syncthreads();
        if (more) {
#pragma unroll
            for (int p = 0; p < AF4; p++) { int f = tid + p*THREADS; int r = f/KV, c4 = f%KV;
                As[c4*4+0][r]=pa[p].x; As[c4*4+1][r]=pa[p].y; As[c4*4+2][r]=pa[p].z; As[c4*4+3][r]=pa[p].w; }
#pragma unroll
            for (int p = 0; p < WF4; p++) { int f = tid + p*THREADS; int r = f/KV, c4 = f%KV;
                Ws[c4*4+0][r]=pw[p].x; Ws[c4*4+1][r]=pw[p].y; Ws[c4*4+2][r]=pw[p].z; Ws[c4*4+3][r]=pw[p].w; }
            __syncthreads();
        }
    }

#pragma unroll
    for (int i = 0; i < TM; i++) {
        int cm = m0 + ty*TM + i;
#pragma unroll
        for (int g = 0; g < TN/4; g++) {
            int ng = n0 + g*(BN/2) + tx*4;
            float2 v01 = unpack2(acc2[i][g*2 + 0]);
            float2 v23 = unpack2(acc2[i][g*2 + 1]);
            float4 bb = *(const float4*)(bias + ng);
            float4 v;
            v.x = fmaxf(v01.x + bb.x, 0.f);
            v.y = fmaxf(v01.y + bb.y, 0.f);
            v.z = fmaxf(v23.x + bb.z, 0.f);
            v.w = fmaxf(v23.y + bb.w, 0.f);
            if constexpr (MODE == 2) {
                float4 r = *(const float4*)(g_xh + (size_t)cm*Ndim + ng);
                int c = ng >> 7;                 // o = c*128 + l
                float sc = ssc[c], sh = ssh[c];
                v.x = (v.x + r.x)*sc + sh;
                v.y = (v.y + r.y)*sc + sh;
                v.z = (v.z + r.z)*sc + sh;
                v.w = (v.w + r.w)*sc + sh;
            }
            *(float4*)(C + (size_t)cm*Ndim + ng) = v;
        }
    }
}

// ---------------- launch ----------------------------------------------------
extern "C" void kernel_launch(void* const* d_in, const int* in_sizes, int n_in,
                              void* d_out, int out_size) {
    const float* x   = (const float*)d_in[0];
    const float* Wq  = (const float*)d_in[1];
    const float* bq  = (const float*)d_in[2];
    const float* Wk  = (const float*)d_in[3];
    const float* bk  = (const float*)d_in[4];
    const float* Wv  = (const float*)d_in[5];
    const float* bv  = (const float*)d_in[6];
    const float* Wo  = (const float*)d_in[7];
    const float* bo  = (const float*)d_in[8];
    const float* g1  = (const float*)d_in[9];
    const float* be1 = (const float*)d_in[10];
    const float* mu1 = (const float*)d_in[11];
    const float* va1 = (const float*)d_in[12];
    const float* W1  = (const float*)d_in[13];
    const float* b1  = (const float*)d_in[14];
    const float* W2  = (const float*)d_in[15];
    const float* b2  = (const float*)d_in[16];
    const float* g2  = (const float*)d_in[17];
    const float* be2 = (const float*)d_in[18];
    const float* mu2 = (const float*)d_in[19];
    const float* va2 = (const float*)d_in[20];
    const int*   idxraw = (const int*)d_in[21];
    float* out = (float*)d_out;

    k_idx<<<(SQ*UU + 255)/256, 256>>>(idxraw);
    k_qkv<<<SQ, LT>>>(x, Wq, bq, Wk, bk, Wv, bv);
    k_sampleM<<<LH, SQ>>>();
    k_topk<<<LH, SQ>>>();
    k_attn<<<LH, 256>>>();
    k_ctx<<<LH, SQ>>>();
    k_out1<<<SQ, LT>>>(x, Wo, bo, g1, be1, mu1, va1);
    k_gemm<128,128,16,8,8,1><<<dim3(NH/128, SQ/128), 256>>>(
        W1, b1, nullptr, KF, NH, nullptr, nullptr, nullptr, nullptr);
    k_gemm<128, 64,16,8,4,2><<<dim3(KF/64, SQ/128), 256>>>(
        W2, b2, out, NH, KF, g2, be2, mu2, va2);
    (void)in_sizes; (void)n_in; (void)out_size;
}

// round 14
// speedup vs baseline: 2.8413x; 2.8413x over previous
#include <cuda_runtime.h>
#include <cmath>

// ---------------- problem constants ----------------
#define LT   128            // time dim (attention "batch")
#define SQ   512            // sequence dim (original batch B)
#define HH   8
#define DD   4
#define DM   32
#define UU   35             // top-k / sample count
#define CC   32
#define KF   4096           // C*L  (FFN inner dim A)
#define NH   8192           // FFN hidden dim
#define LH   (LT*HH)        // 1024

// ---------------- scratch (device globals; allocation-free) ----------------
__device__ __align__(16) float g_Q[LH*SQ*DD];
__device__ __align__(16) float g_K[LH*SQ*DD];
__device__ __align__(16) float g_V[LH*SQ*DD];
__device__ __align__(16) float g_ctx[LH*SQ*DD];
__device__ float g_M[LH*SQ];
__device__ int   g_Mtop[LH*UU];
__device__ __align__(16) float g_upd[LH*UU*DD];
__device__ int   g_sidx[SQ*UU];
__device__ __align__(16) float g_xh[SQ*KF];       // BN1 output == FFN input (B, C*L)
__device__ __align__(16) float g_hidden[SQ*NH];   // FFN hidden (B, 8192)

// ---------------- async-copy + mma helpers ----------------------------------
__device__ __forceinline__ void cpasync16(void* smem_dst, const void* gmem_src) {
    unsigned d = (unsigned)__cvta_generic_to_shared(smem_dst);
    asm volatile("cp.async.cg.shared.global [%0], [%1], 16;\n" :: "r"(d), "l"(gmem_src));
}
__device__ __forceinline__ void cp_commit() {
    asm volatile("cp.async.commit_group;\n" ::: "memory");
}
__device__ __forceinline__ void cp_wait1() {
    asm volatile("cp.async.wait_group 1;\n" ::: "memory");
}
__device__ __forceinline__ void cp_wait0() {
    asm volatile("cp.async.wait_group 0;\n" ::: "memory");
}
__device__ __forceinline__ void mma_tf32(float* c, const unsigned* a, const unsigned* b) {
    asm volatile(
        "mma.sync.aligned.m16n8k8.row.col.f32.tf32.tf32.f32 "
        "{%0,%1,%2,%3}, {%4,%5,%6,%7}, {%8,%9}, {%0,%1,%2,%3};\n"
        : "+f"(c[0]), "+f"(c[1]), "+f"(c[2]), "+f"(c[3])
        : "r"(a[0]), "r"(a[1]), "r"(a[2]), "r"(a[3]), "r"(b[0]), "r"(b[1]));
}

// ---------------- 0: index dtype normalize (int64 or int32 -> int32) --------
__global__ void k_idx(const int* __restrict__ raw) {
    bool is64 = true;
#pragma unroll
    for (int i = 1; i < 128; i += 2)
        if (raw[i] != 0) is64 = false;     // int64 little-endian high words are 0
    int t = blockIdx.x * blockDim.x + threadIdx.x;
    if (t < SQ * UU) g_sidx[t] = is64 ? raw[2 * t] : raw[t];
}

// ---------------- 1: QKV projection ----------------------------------------
__global__ void k_qkv(const float* __restrict__ x,
                      const float* __restrict__ Wq, const float* __restrict__ bq,
                      const float* __restrict__ Wk, const float* __restrict__ bk,
                      const float* __restrict__ Wv, const float* __restrict__ bv)
{
    __shared__ float sW[3 * DM * DM];
    __shared__ float sb[3 * DM];
    int l = threadIdx.x;   // 0..127
    int b = blockIdx.x;    // 0..511
    for (int i = l; i < DM * DM; i += LT) {
        sW[i] = Wq[i]; sW[DM*DM + i] = Wk[i]; sW[2*DM*DM + i] = Wv[i];
    }
    if (l < DM) { sb[l] = bq[l]; sb[DM + l] = bk[l]; sb[2*DM + l] = bv[l]; }
    __syncthreads();

    float xr[DM];
#pragma unroll
    for (int c = 0; c < DM; c++) xr[c] = x[(b * CC + c) * LT + l];

    for (int m = 0; m < DM; m++) {
        float aq = sb[m], ak = sb[DM + m], av = sb[2*DM + m];
#pragma unroll
        for (int c = 0; c < DM; c++) {
            float xv = xr[c];
            aq = fmaf(sW[m*DM + c],          xv, aq);
            ak = fmaf(sW[DM*DM + m*DM + c],  xv, ak);
            av = fmaf(sW[2*DM*DM + m*DM + c],xv, av);
        }
        int h = m >> 2, d = m & 3;
        int o = ((l * HH + h) * SQ + b) * DD + d;
        g_Q[o] = aq; g_K[o] = ak; g_V[o] = av;
    }
}

// ---------------- 2: sampled QK -> M = max - mean ---------------------------
__global__ void k_sampleM() {
    __shared__ float4 Ksh[SQ];
    int lh = blockIdx.x;
    int s  = threadIdx.x;  // 0..511
    Ksh[s] = ((const float4*)g_K)[lh * SQ + s];
    __syncthreads();
    float4 q = ((const float4*)g_Q)[lh * SQ + s];
    float mx = -1e30f, sm = 0.f;
    const int* ip = &g_sidx[s * UU];
#pragma unroll 5
    for (int j = 0; j < UU; j++) {
        float4 k = Ksh[ip[j]];
        float d = q.x*k.x + q.y*k.y + q.z*k.z + q.w*k.w;
        mx = fmaxf(mx, d); sm += d;
    }
    g_M[lh * SQ + s] = mx - sm * (1.0f / SQ);
}

// ---------------- 3: top-35, one warp per lh, register-resident, no bar -----
// key = (monotone(float) << 32) | (511 - s): max key = max value, tie -> min s.
__global__ void k_topk() {
    int warp = threadIdx.x >> 5, lane = threadIdx.x & 31;
    int lh = blockIdx.x * 4 + warp;
    unsigned long long key[16];
#pragma unroll
    for (int t = 0; t < 16; t++) {
        int s = t * 32 + lane;                      // coalesced
        unsigned u = __float_as_uint(g_M[lh * SQ + s]);
        u = (u & 0x80000000u) ? ~u : (u | 0x80000000u);
        key[t] = ((unsigned long long)u << 32) | (unsigned)(SQ - 1 - s);
    }
    for (int it = 0; it < UU; it++) {
        unsigned long long best = 0ull;
#pragma unroll
        for (int t = 0; t < 16; t++) best = (key[t] > best) ? key[t] : best;
#pragma unroll
        for (int o = 16; o > 0; o >>= 1) {
            unsigned long long v = __shfl_xor_sync(0xffffffffu, best, o);
            best = (v > best) ? v : best;
        }
        int s = (SQ - 1) - (int)(best & 0xffffffffull);
        if (lane == 0) g_Mtop[lh * UU + it] = s;
        if ((s & 31) == lane) {
            int tt = s >> 5;
#pragma unroll
            for (int t = 0; t < 16; t++) if (t == tt) key[t] = 0ull;
        }
    }
}

// ---------------- 4: sparse causal attention -> upd -------------------------
__global__ void k_attn() {
    __shared__ float4 Ksh[SQ];
    __shared__ float4 Vsh[SQ];
    int lh = blockIdx.x;
    int tid = threadIdx.x;          // 256
    const float4* Kp = (const float4*)g_K + lh * SQ;
    const float4* Vp = (const float4*)g_V + lh * SQ;
    for (int i = tid; i < SQ; i += 256) { Ksh[i] = Kp[i]; Vsh[i] = Vp[i]; }
    __syncthreads();
    int w = tid >> 5, lane = tid & 31;
    for (int u = w; u < UU; u += 8) {
        int su = g_Mtop[lh * UU + u];
        float4 q = ((const float4*)g_Q)[lh * SQ + su];
        q.x *= 0.5f; q.y *= 0.5f; q.z *= 0.5f; q.w *= 0.5f;   // 1/sqrt(D)
        int nk = su + 1;                                       // causal: k <= su
        float mx = -1e30f;
        for (int k = lane; k < nk; k += 32) {
            float4 kv = Ksh[k];
            mx = fmaxf(mx, q.x*kv.x + q.y*kv.y + q.z*kv.z + q.w*kv.w);
        }
#pragma unroll
        for (int o = 16; o > 0; o >>= 1) mx = fmaxf(mx, __shfl_xor_sync(0xffffffffu, mx, o));
        float sum = 0.f, ax = 0.f, ay = 0.f, az = 0.f, aw = 0.f;
        for (int k = lane; k < nk; k += 32) {
            float4 kv = Ksh[k];
            float d = q.x*kv.x + q.y*kv.y + q.z*kv.z + q.w*kv.w;
            float e = expf(d - mx);
            float4 vv = Vsh[k];
            sum += e; ax += e*vv.x; ay += e*vv.y; az += e*vv.z; aw += e*vv.w;
        }
#pragma unroll
        for (int o = 16; o > 0; o >>= 1) {
            sum += __shfl_xor_sync(0xffffffffu, sum, o);
            ax  += __shfl_xor_sync(0xffffffffu, ax,  o);
            ay  += __shfl_xor_sync(0xffffffffu, ay,  o);
            az  += __shfl_xor_sync(0xffffffffu, az,  o);
            aw  += __shfl_xor_sync(0xffffffffu, aw,  o);
        }
        if (lane == 0) {
            float inv = 1.0f / sum;
            ((float4*)g_upd)[lh * UU + u] = make_float4(ax*inv, ay*inv, az*inv, aw*inv);
        }
    }
}

// ---------------- 5: cumsum(V) + scatter upd -> ctx -------------------------
__global__ void k_ctx() {
    __shared__ float4 buf[SQ];
    int lh = blockIdx.x, s = threadIdx.x;
    buf[s] = ((const float4*)g_V)[lh * SQ + s];
    __syncthreads();
    for (int off = 1; off < SQ; off <<= 1) {
        float4 a = buf[s];
        float4 b = make_float4(0.f, 0.f, 0.f, 0.f);
        if (s >= off) b = buf[s - off];
        __syncthreads();
        a.x += b.x; a.y += b.y; a.z += b.z; a.w += b.w;
        buf[s] = a;
        __syncthreads();
    }
    if (s < UU) {
        int su = g_Mtop[lh * UU + s];
        buf[su] = ((const float4*)g_upd)[lh * UU + s];
    }
    __syncthreads();
    ((float4*)g_ctx)[lh * SQ + s] = buf[s];
}

// ---------------- 6: Wo projection + relu + residual + BN1 -> xh ------------
__global__ void k_out1(const float* __restrict__ x,
                       const float* __restrict__ Wo, const float* __restrict__ bo,
                       const float* __restrict__ g1, const float* __restrict__ be1,
                       const float* __restrict__ mu1, const float* __restrict__ va1)
{
    __shared__ float sW[DM * DM];
    __shared__ float sbo[DM], ssc[DM], ssh[DM];
    int l = threadIdx.x, b = blockIdx.x;
    for (int i = l; i < DM * DM; i += LT) sW[i] = Wo[i];
    if (l < DM) {
        sbo[l] = bo[l];
        float sc = g1[l] * rsqrtf(va1[l] + 1e-5f);
        ssc[l] = sc; ssh[l] = be1[l] - mu1[l] * sc;
    }
    __syncthreads();

    float cr[DM];
#pragma unroll
    for (int h = 0; h < HH; h++) {
        float4 t = ((const float4*)g_ctx)[(l * HH + h) * SQ + b];
        cr[h*4+0] = t.x; cr[h*4+1] = t.y; cr[h*4+2] = t.z; cr[h*4+3] = t.w;
    }
    for (int c = 0; c < DM; c++) {
        float a = sbo[c];
#pragma unroll
        for (int m = 0; m < DM; m++) a = fmaf(sW[c*DM + m], cr[m], a);
        a = fmaxf(a, 0.f) + x[(b * CC + c) * LT + l];
        g_xh[(b * CC + c) * LT + l] = a * ssc[c] + ssh[c];
    }
}

// ---------------- 7/8: FFN GEMMs, tf32 mma.sync, cp.async double-buffer -----
// C[m][n] = epi( sum_k A[m][k] * W[n][k] + bias[n] )
// MODE 1: A=g_xh    (512x4096), out=g_hidden, epi = relu
// MODE 2: A=g_hidden(512x8192), out=d_out,    epi = relu + xh-residual + BN2
// Tiles stored row-major [rows][BK+4]: st.128 fill and frag lds.32 both
// conflict-free (bank = (4g+tg)%32, 32 distinct).
template<int BM,int BN,int WARPS_M,int WARPS_N,int MODE>
__global__ void __launch_bounds__(256)
k_tc(const float* __restrict__ W, const float* __restrict__ bias,
     float* __restrict__ Cext, int Kdim, int Ndim,
     const float* __restrict__ g2, const float* __restrict__ be2,
     const float* __restrict__ mu2, const float* __restrict__ va2)
{
    constexpr int BK = 32, SW = BK + 4;
    constexpr int WM = BM / WARPS_M, WN = BN / WARPS_N;
    constexpr int TMT = WM / 16, TNT = WN / 8;
    constexpr int APF = BM * (BK/4) / 256;
    constexpr int WPF = BN * (BK/4) / 256;
    extern __shared__ float sm[];
    float* As = sm;                       // [2][BM][SW]
    float* Ws = sm + 2 * BM * SW;         // [2][BN][SW]
    __shared__ float ssc[CC], ssh[CC];

    const float* __restrict__ A = (MODE == 1) ? g_xh : g_hidden;
    float* __restrict__ C = (MODE == 1) ? g_hidden : Cext;

    int tid  = threadIdx.x;
    int wid  = tid >> 5, lane = tid & 31;
    int g    = lane >> 2, tg = lane & 3;
    int wm0  = (wid / WARPS_N) * WM;
    int wn0  = (wid % WARPS_N) * WN;
    int m0   = blockIdx.y * BM;
    int n0   = blockIdx.x * BN;

    if (MODE == 2 && tid < CC) {
        float sc = g2[tid] * rsqrtf(va2[tid] + 1e-5f);
        ssc[tid] = sc; ssh[tid] = be2[tid] - mu2[tid] * sc;
    }

    auto ldt = [&](int t, int buf) {
        int kt = t * BK;
#pragma unroll
        for (int p = 0; p < APF; p++) {
            int f = tid + p * 256, r = f >> 3, c4 = (f & 7) * 4;
            cpasync16(&As[(buf * BM + r) * SW + c4],
                      A + (size_t)(m0 + r) * Kdim + kt + c4);
        }
#pragma unroll
        for (int p = 0; p < WPF; p++) {
            int f = tid + p * 256, r = f >> 3, c4 = (f & 7) * 4;
            cpasync16(&Ws[(buf * BN + r) * SW + c4],
                      W + (size_t)(n0 + r) * Kdim + kt + c4);
        }
    };

    float acc[TMT][TNT][4];
#pragma unroll
    for (int i = 0; i < TMT; i++)
#pragma unroll
        for (int j = 0; j < TNT; j++)
#pragma unroll
            for (int q = 0; q < 4; q++) acc[i][j][q] = 0.f;

    int nT = Kdim / BK;
    ldt(0, 0); cp_commit();
    ldt(1, 1); cp_commit();
    cp_wait1(); __syncthreads();

    for (int t = 0; t < nT; t++) {
        const float* Ab = &As[(t & 1) * BM * SW];
        const float* Wb = &Ws[(t & 1) * BN * SW];
#pragma unroll
        for (int kk = 0; kk < BK / 8; kk++) {
            int k0 = kk * 8;
            unsigned af[TMT][4], bf[TNT][2];
#pragma unroll
            for (int i = 0; i < TMT; i++) {
                const float* base = Ab + (wm0 + i * 16 + g) * SW + k0 + tg;
                af[i][0] = __float_as_uint(base[0]);
                af[i][1] = __float_as_uint(base[8 * SW]);
                af[i][2] = __float_as_uint(base[4]);
                af[i][3] = __float_as_uint(base[8 * SW + 4]);
            }
#pragma unroll
            for (int j = 0; j < TNT; j++) {
                const float* base = Wb + (wn0 + j * 8 + g) * SW + k0 + tg;
                bf[j][0] = __float_as_uint(base[0]);
                bf[j][1] = __float_as_uint(base[4]);
            }
#pragma unroll
            for (int i = 0; i < TMT; i++)
#pragma unroll
                for (int j = 0; j < TNT; j++)
                    mma_tf32(acc[i][j], af[i], bf[j]);
        }
        if (t + 2 < nT) {
            __syncthreads();            // buffer (t&1) fully consumed by all warps
            ldt(t + 2, t & 1);
            cp_commit();
            cp_wait1();                 // tile t+1 resident
            __syncthreads();
        } else if (t + 1 < nT) {
            cp_wait0();                 // last prefetched tile resident
            __syncthreads();
        }
    }

    // epilogue: c0,c1 -> (row, nb..nb+1); c2,c3 -> (row+8, nb..nb+1)
#pragma unroll
    for (int i = 0; i < TMT; i++) {
        int r0 = m0 + wm0 + i * 16 + g;
#pragma unroll
        for (int j = 0; j < TNT; j++) {
            int nb = n0 + wn0 + j * 8 + 2 * tg;
            float2 bb = *(const float2*)(bias + nb);
#pragma unroll
            for (int h = 0; h < 2; h++) {
                int row = r0 + h * 8;
                float v0 = fmaxf(acc[i][j][h * 2 + 0] + bb.x, 0.f);
                float v1 = fmaxf(acc[i][j][h * 2 + 1] + bb.y, 0.f);
                if constexpr (MODE == 2) {
                    float2 rr = *(const float2*)(g_xh + (size_t)row * Ndim + nb);
                    int c = nb >> 7;
                    float sc = ssc[c], sh = ssh[c];
                    v0 = (v0 + rr.x) * sc + sh;
                    v1 = (v1 + rr.y) * sc + sh;
                }
                *(float2*)(C + (size_t)row * Ndim + nb) = make_float2(v0, v1);
            }
        }
    }
}

// ---------------- launch ----------------------------------------------------
extern "C" void kernel_launch(void* const* d_in, const int* in_sizes, int n_in,
                              void* d_out, int out_size) {
    const float* x   = (const float*)d_in[0];
    const float* Wq  = (const float*)d_in[1];
    const float* bq  = (const float*)d_in[2];
    const float* Wk  = (const float*)d_in[3];
    const float* bk  = (const float*)d_in[4];
    const float* Wv  = (const float*)d_in[5];
    const float* bv  = (const float*)d_in[6];
    const float* Wo  = (const float*)d_in[7];
    const float* bo  = (const float*)d_in[8];
    const float* g1  = (const float*)d_in[9];
    const float* be1 = (const float*)d_in[10];
    const float* mu1 = (const float*)d_in[11];
    const float* va1 = (const float*)d_in[12];
    const float* W1  = (const float*)d_in[13];
    const float* b1  = (const float*)d_in[14];
    const float* W2  = (const float*)d_in[15];
    const float* b2  = (const float*)d_in[16];
    const float* g2  = (const float*)d_in[17];
    const float* be2 = (const float*)d_in[18];
    const float* mu2 = (const float*)d_in[19];
    const float* va2 = (const float*)d_in[20];
    const int*   idxraw = (const int*)d_in[21];
    float* out = (float*)d_out;

    constexpr int SW = 36;
    int smem1 = 2 * (128 + 128) * SW * 4;   // 73728 B
    int smem2 = 2 * (128 + 64)  * SW * 4;   // 55296 B
    cudaFuncSetAttribute(k_tc<128,128,2,4,1>,
                         cudaFuncAttributeMaxDynamicSharedMemorySize, smem1);
    cudaFuncSetAttribute(k_tc<128,64,4,2,2>,
                         cudaFuncAttributeMaxDynamicSharedMemorySize, smem2);

    k_idx<<<(SQ*UU + 255)/256, 256>>>(idxraw);
    k_qkv<<<SQ, LT>>>(x, Wq, bq, Wk, bk, Wv, bv);
    k_sampleM<<<LH, SQ>>>();
    k_topk<<<LH/4, 128>>>();
    k_attn<<<LH, 256>>>();
    k_ctx<<<LH, SQ>>>();
    k_out1<<<SQ, LT>>>(x, Wo, bo, g1, be1, mu1, va1);
    k_tc<128,128,2,4,1><<<dim3(NH/128, SQ/128), 256, smem1>>>(
        W1, b1, nullptr, KF, NH, nullptr, nullptr, nullptr, nullptr);
    k_tc<128,64,4,2,2><<<dim3(KF/64, SQ/128), 256, smem2>>>(
        W2, b2, out, NH, KF, g2, be2, mu2, va2);
    (void)in_sizes; (void)n_in; (void)out_size;
}

// round 17
// speedup vs baseline: 2.8638x; 1.0079x over previous
#include <cuda_runtime.h>
#include <cmath>

// ---------------- problem constants ----------------
#define LT   128            // time dim (attention "batch")
#define SQ   512            // sequence dim (original batch B)
#define HH   8
#define DD   4
#define DM   32
#define UU   35             // top-k / sample count
#define CC   32
#define KF   4096           // C*L  (FFN inner dim A)
#define NH   8192           // FFN hidden dim
#define LH   (LT*HH)        // 1024

// ---------------- scratch (device globals; allocation-free) ----------------
__device__ __align__(16) float g_Q[LH*SQ*DD];
__device__ __align__(16) float g_K[LH*SQ*DD];
__device__ __align__(16) float g_V[LH*SQ*DD];
__device__ __align__(16) float g_ctx[LH*SQ*DD];
__device__ float g_M[LH*SQ];
__device__ int   g_Mtop[LH*UU];
__device__ __align__(16) float g_upd[LH*UU*DD];
__device__ int   g_sidx[SQ*UU];
__device__ __align__(16) float g_xh[SQ*KF];       // BN1 output == FFN input (B, C*L)
__device__ __align__(16) float g_hidden[SQ*NH];   // FFN hidden (B, 8192)

// ---------------- async-copy + mma helpers ----------------------------------
__device__ __forceinline__ void cpasync16(void* smem_dst, const void* gmem_src) {
    unsigned d = (unsigned)__cvta_generic_to_shared(smem_dst);
    asm volatile("cp.async.cg.shared.global [%0], [%1], 16;\n" :: "r"(d), "l"(gmem_src));
}
__device__ __forceinline__ void cp_commit() {
    asm volatile("cp.async.commit_group;\n" ::: "memory");
}
__device__ __forceinline__ void cp_wait1() {
    asm volatile("cp.async.wait_group 1;\n" ::: "memory");
}
__device__ __forceinline__ void mma_tf32(float* c, const unsigned* a, const unsigned* b) {
    asm volatile(
        "mma.sync.aligned.m16n8k8.row.col.f32.tf32.tf32.f32 "
        "{%0,%1,%2,%3}, {%4,%5,%6,%7}, {%8,%9}, {%0,%1,%2,%3};\n"
        : "+f"(c[0]), "+f"(c[1]), "+f"(c[2]), "+f"(c[3])
        : "r"(a[0]), "r"(a[1]), "r"(a[2]), "r"(a[3]), "r"(b[0]), "r"(b[1]));
}

// ---------------- 0: index dtype normalize (int64 or int32 -> int32) --------
__global__ void k_idx(const int* __restrict__ raw) {
    bool is64 = true;
#pragma unroll
    for (int i = 1; i < 128; i += 2)
        if (raw[i] != 0) is64 = false;     // int64 little-endian high words are 0
    int t = blockIdx.x * blockDim.x + threadIdx.x;
    if (t < SQ * UU) g_sidx[t] = is64 ? raw[2 * t] : raw[t];
}

// ---------------- 1: QKV projection ----------------------------------------
__global__ void k_qkv(const float* __restrict__ x,
                      const float* __restrict__ Wq, const float* __restrict__ bq,
                      const float* __restrict__ Wk, const float* __restrict__ bk,
                      const float* __restrict__ Wv, const float* __restrict__ bv)
{
    __shared__ float sW[3 * DM * DM];
    __shared__ float sb[3 * DM];
    int l = threadIdx.x;   // 0..127
    int b = blockIdx.x;    // 0..511
    for (int i = l; i < DM * DM; i += LT) {
        sW[i] = Wq[i]; sW[DM*DM + i] = Wk[i]; sW[2*DM*DM + i] = Wv[i];
    }
    if (l < DM) { sb[l] = bq[l]; sb[DM + l] = bk[l]; sb[2*DM + l] = bv[l]; }
    __syncthreads();

    float xr[DM];
#pragma unroll
    for (int c = 0; c < DM; c++) xr[c] = x[(b * CC + c) * LT + l];

    for (int m = 0; m < DM; m++) {
        float aq = sb[m], ak = sb[DM + m], av = sb[2*DM + m];
#pragma unroll
        for (int c = 0; c < DM; c++) {
            float xv = xr[c];
            aq = fmaf(sW[m*DM + c],          xv, aq);
            ak = fmaf(sW[DM*DM + m*DM + c],  xv, ak);
            av = fmaf(sW[2*DM*DM + m*DM + c],xv, av);
        }
        int h = m >> 2, d = m & 3;
        int o = ((l * HH + h) * SQ + b) * DD + d;
        g_Q[o] = aq; g_K[o] = ak; g_V[o] = av;
    }
}

// ---------------- 2: sampled QK -> M = max - mean ---------------------------
__global__ void k_sampleM() {
    __shared__ float4 Ksh[SQ];
    int lh = blockIdx.x;
    int s  = threadIdx.x;  // 0..511
    Ksh[s] = ((const float4*)g_K)[lh * SQ + s];
    __syncthreads();
    float4 q = ((const float4*)g_Q)[lh * SQ + s];
    float mx = -1e30f, sm = 0.f;
    const int* ip = &g_sidx[s * UU];
#pragma unroll 5
    for (int j = 0; j < UU; j++) {
        float4 k = Ksh[ip[j]];
        float d = q.x*k.x + q.y*k.y + q.z*k.z + q.w*k.w;
        mx = fmaxf(mx, d); sm += d;
    }
    g_M[lh * SQ + s] = mx - sm * (1.0f / SQ);
}

// ---------------- 3: top-35, one warp per lh, register-resident, no bar -----
__global__ void k_topk() {
    int warp = threadIdx.x >> 5, lane = threadIdx.x & 31;
    int lh = blockIdx.x * 4 + warp;
    unsigned long long key[16];
#pragma unroll
    for (int t = 0; t < 16; t++) {
        int s = t * 32 + lane;                      // coalesced
        unsigned u = __float_as_uint(g_M[lh * SQ + s]);
        u = (u & 0x80000000u) ? ~u : (u | 0x80000000u);
        key[t] = ((unsigned long long)u << 32) | (unsigned)(SQ - 1 - s);
    }
    for (int it = 0; it < UU; it++) {
        unsigned long long best = 0ull;
#pragma unroll
        for (int t = 0; t < 16; t++) best = (key[t] > best) ? key[t] : best;
#pragma unroll
        for (int o = 16; o > 0; o >>= 1) {
            unsigned long long v = __shfl_xor_sync(0xffffffffu, best, o);
            best = (v > best) ? v : best;
        }
        int s = (SQ - 1) - (int)(best & 0xffffffffull);
        if (lane == 0) g_Mtop[lh * UU + it] = s;
        if ((s & 31) == lane) {
            int tt = s >> 5;
#pragma unroll
            for (int t = 0; t < 16; t++) if (t == tt) key[t] = 0ull;
        }
    }
}

// ---------------- 4: sparse causal attention -> upd -------------------------
__global__ void k_attn() {
    __shared__ float4 Ksh[SQ];
    __shared__ float4 Vsh[SQ];
    int lh = blockIdx.x;
    int tid = threadIdx.x;          // 256
    const float4* Kp = (const float4*)g_K + lh * SQ;
    const float4* Vp = (const float4*)g_V + lh * SQ;
    for (int i = tid; i < SQ; i += 256) { Ksh[i] = Kp[i]; Vsh[i] = Vp[i]; }
    __syncthreads();
    int w = tid >> 5, lane = tid & 31;
    for (int u = w; u < UU; u += 8) {
        int su = g_Mtop[lh * UU + u];
        float4 q = ((const float4*)g_Q)[lh * SQ + su];
        q.x *= 0.5f; q.y *= 0.5f; q.z *= 0.5f; q.w *= 0.5f;   // 1/sqrt(D)
        int nk = su + 1;                                       // causal: k <= su
        float mx = -1e30f;
        for (int k = lane; k < nk; k += 32) {
            float4 kv = Ksh[k];
            mx = fmaxf(mx, q.x*kv.x + q.y*kv.y + q.z*kv.z + q.w*kv.w);
        }
#pragma unroll
        for (int o = 16; o > 0; o >>= 1) mx = fmaxf(mx, __shfl_xor_sync(0xffffffffu, mx, o));
        float sum = 0.f, ax = 0.f, ay = 0.f, az = 0.f, aw = 0.f;
        for (int k = lane; k < nk; k += 32) {
            float4 kv = Ksh[k];
            float d = q.x*kv.x + q.y*kv.y + q.z*kv.z + q.w*kv.w;
            float e = expf(d - mx);
            float4 vv = Vsh[k];
            sum += e; ax += e*vv.x; ay += e*vv.y; az += e*vv.z; aw += e*vv.w;
        }
#pragma unroll
        for (int o = 16; o > 0; o >>= 1) {
            sum += __shfl_xor_sync(0xffffffffu, sum, o);
            ax  += __shfl_xor_sync(0xffffffffu, ax,  o);
            ay  += __shfl_xor_sync(0xffffffffu, ay,  o);
            az  += __shfl_xor_sync(0xffffffffu, az,  o);
            aw  += __shfl_xor_sync(0xffffffffu, aw,  o);
        }
        if (lane == 0) {
            float inv = 1.0f / sum;
            ((float4*)g_upd)[lh * UU + u] = make_float4(ax*inv, ay*inv, az*inv, aw*inv);
        }
    }
}

// ---------------- 5: cumsum(V) + scatter upd -> ctx -------------------------
__global__ void k_ctx() {
    __shared__ float4 buf[SQ];
    int lh = blockIdx.x, s = threadIdx.x;
    buf[s] = ((const float4*)g_V)[lh * SQ + s];
    __syncthreads();
    for (int off = 1; off < SQ; off <<= 1) {
        float4 a = buf[s];
        float4 b = make_float4(0.f, 0.f, 0.f, 0.f);
        if (s >= off) b = buf[s - off];
        __syncthreads();
        a.x += b.x; a.y += b.y; a.z += b.z; a.w += b.w;
        buf[s] = a;
        __syncthreads();
    }
    if (s < UU) {
        int su = g_Mtop[lh * UU + s];
        buf[su] = ((const float4*)g_upd)[lh * UU + s];
    }
    __syncthreads();
    ((float4*)g_ctx)[lh * SQ + s] = buf[s];
}

// ---------------- 6: Wo projection + relu + residual + BN1 -> xh ------------
__global__ void k_out1(const float* __restrict__ x,
                       const float* __restrict__ Wo, const float* __restrict__ bo,
                       const float* __restrict__ g1, const float* __restrict__ be1,
                       const float* __restrict__ mu1, const float* __restrict__ va1)
{
    __shared__ float sW[DM * DM];
    __shared__ float sbo[DM], ssc[DM], ssh[DM];
    int l = threadIdx.x, b = blockIdx.x;
    for (int i = l; i < DM * DM; i += LT) sW[i] = Wo[i];
    if (l < DM) {
        sbo[l] = bo[l];
        float sc = g1[l] * rsqrtf(va1[l] + 1e-5f);
        ssc[l] = sc; ssh[l] = be1[l] - mu1[l] * sc;
    }
    __syncthreads();

    float cr[DM];
#pragma unroll
    for (int h = 0; h < HH; h++) {
        float4 t = ((const float4*)g_ctx)[(l * HH + h) * SQ + b];
        cr[h*4+0] = t.x; cr[h*4+1] = t.y; cr[h*4+2] = t.z; cr[h*4+3] = t.w;
    }
    for (int c = 0; c < DM; c++) {
        float a = sbo[c];
#pragma unroll
        for (int m = 0; m < DM; m++) a = fmaf(sW[c*DM + m], cr[m], a);
        a = fmaxf(a, 0.f) + x[(b * CC + c) * LT + l];
        g_xh[(b * CC + c) * LT + l] = a * ssc[c] + ssh[c];
    }
}

// ---------------- 7/8: FFN GEMMs, tf32 mma.sync, cp.async double-buffer -----
// C[m][n] = epi( sum_k A[m][k] * W[n][k] + bias[n] )
// MODE 1: A=g_xh    (512x4096), out=g_hidden, epi = relu
// MODE 2: A=g_hidden(512x8192), out=d_out,    epi = relu + xh-residual + BN2
// Tiles stored row-major [rows][BK+4]: st.128 fill and frag lds.32 both
// conflict-free (bank = (4g+tg)%32, 32 distinct).
// __launch_bounds__(256, 2): cap regs at 128 so 2 CTAs co-reside per SM
// (2x73728B smem fits in 228KB) -> 4 warps/SMSP to hide fallback-HMMA latency.
template<int BM,int BN,int WARPS_M,int WARPS_N,int MODE>
__global__ void __launch_bounds__(256, 2)
k_tc(const float* __restrict__ W, const float* __restrict__ bias,
     float* __restrict__ Cext, int Kdim, int Ndim,
     const float* __restrict__ g2, const float* __restrict__ be2,
     const float* __restrict__ mu2, const float* __restrict__ va2)
{
    constexpr int BK = 32, SW = BK + 4;
    constexpr int WM = BM / WARPS_M, WN = BN / WARPS_N;
    constexpr int TMT = WM / 16, TNT = WN / 8;
    constexpr int APF = BM * (BK/4) / 256;
    constexpr int WPF = BN * (BK/4) / 256;
    extern __shared__ float sm[];
    float* As = sm;                       // [2][BM][SW]
    float* Ws = sm + 2 * BM * SW;         // [2][BN][SW]
    __shared__ float ssc[CC], ssh[CC];

    const float* __restrict__ A = (MODE == 1) ? g_xh : g_hidden;
    float* __restrict__ C = (MODE == 1) ? g_hidden : Cext;

    int tid  = threadIdx.x;
    int wid  = tid >> 5, lane = tid & 31;
    int g    = lane >> 2, tg = lane & 3;
    int wm0  = (wid / WARPS_N) * WM;
    int wn0  = (wid % WARPS_N) * WN;
    int m0   = blockIdx.y * BM;
    int n0   = blockIdx.x * BN;

    if (MODE == 2 && tid < CC) {
        float sc = g2[tid] * rsqrtf(va2[tid] + 1e-5f);
        ssc[tid] = sc; ssh[tid] = be2[tid] - mu2[tid] * sc;
    }

    auto ldt = [&](int t, int buf) {
        int kt = t * BK;
#pragma unroll
        for (int p = 0; p < APF; p++) {
            int f = tid + p * 256, r = f >> 3, c4 = (f & 7) * 4;
            cpasync16(&As[(buf * BM + r) * SW + c4],
                      A + (size_t)(m0 + r) * Kdim + kt + c4);
        }
#pragma unroll
        for (int p = 0; p < WPF; p++) {
            int f = tid + p * 256, r = f >> 3, c4 = (f & 7) * 4;
            cpasync16(&Ws[(buf * BN + r) * SW + c4],
                      W + (size_t)(n0 + r) * Kdim + kt + c4);
        }
    };

    float acc[TMT][TNT][4];
#pragma unroll
    for (int i = 0; i < TMT; i++)
#pragma unroll
        for (int j = 0; j < TNT; j++)
#pragma unroll
            for (int q = 0; q < 4; q++) acc[i][j][q] = 0.f;

    int nT = Kdim / BK;
    ldt(0, 0); cp_commit();
    ldt(1, 1); cp_commit();
    cp_wait1(); __syncthreads();

    for (int t = 0; t < nT; t++) {
        const float* Ab = &As[(t & 1) * BM * SW];
        const float* Wb = &Ws[(t & 1) * BN * SW];
#pragma unroll
        for (int kk = 0; kk < BK / 8; kk++) {
            int k0 = kk * 8;
            unsigned af[TMT][4], bf[TNT][2];
#pragma unroll
            for (int i = 0; i < TMT; i++) {
                const float* base = Ab + (wm0 + i * 16 + g) * SW + k0 + tg;
                af[i][0] = __float_as_uint(base[0]);
                af[i][1] = __float_as_uint(base[8 * SW]);
                af[i][2] = __float_as_uint(base[4]);
                af[i][3] = __float_as_uint(base[8 * SW + 4]);
            }
#pragma unroll
            for (int j = 0; j < TNT; j++) {
                const float* base = Wb + (wn0 + j * 8 + g) * SW + k0 + tg;
                bf[j][0] = __float_as_uint(base[0]);
                bf[j][1] = __float_as_uint(base[4]);
            }
#pragma unroll
            for (int i = 0; i < TMT; i++)
#pragma unroll
                for (int j = 0; j < TNT; j++)
                    mma_tf32(acc[i][j], af[i], bf[j]);
        }
        __syncthreads();
        if (t + 2 < nT) ldt(t + 2, t & 1);
        cp_commit();
        cp_wait1();
        __syncthreads();
    }

    // epilogue: c0,c1 -> (row, nb..nb+1); c2,c3 -> (row+8, nb..nb+1)
#pragma unroll
    for (int i = 0; i < TMT; i++) {
        int r0 = m0 + wm0 + i * 16 + g;
#pragma unroll
        for (int j = 0; j < TNT; j++) {
            int nb = n0 + wn0 + j * 8 + 2 * tg;
            float2 bb = *(const float2*)(bias + nb);
#pragma unroll
            for (int h = 0; h < 2; h++) {
                int row = r0 + h * 8;
                float v0 = fmaxf(acc[i][j][h * 2 + 0] + bb.x, 0.f);
                float v1 = fmaxf(acc[i][j][h * 2 + 1] + bb.y, 0.f);
                if constexpr (MODE == 2) {
                    float2 rr = *(const float2*)(g_xh + (size_t)row * Ndim + nb);
                    int c = nb >> 7;
                    float sc = ssc[c], sh = ssh[c];
                    v0 = (v0 + rr.x) * sc + sh;
                    v1 = (v1 + rr.y) * sc + sh;
                }
                *(float2*)(C + (size_t)row * Ndim + nb) = make_float2(v0, v1);
            }
        }
    }
}

// ---------------- launch ----------------------------------------------------
extern "C" void kernel_launch(void* const* d_in, const int* in_sizes, int n_in,
                              void* d_out, int out_size) {
    const float* x   = (const float*)d_in[0];
    const float* Wq  = (const float*)d_in[1];
    const float* bq  = (const float*)d_in[2];
    const float* Wk  = (const float*)d_in[3];
    const float* bk  = (const float*)d_in[4];
    const float* Wv  = (const float*)d_in[5];
    const float* bv  = (const float*)d_in[6];
    const float* Wo  = (const float*)d_in[7];
    const float* bo  = (const float*)d_in[8];
    const float* g1  = (const float*)d_in[9];
    const float* be1 = (const float*)d_in[10];
    const float* mu1 = (const float*)d_in[11];
    const float* va1 = (const float*)d_in[12];
    const float* W1  = (const float*)d_in[13];
    const float* b1  = (const float*)d_in[14];
    const float* W2  = (const float*)d_in[15];
    const float* b2  = (const float*)d_in[16];
    const float* g2  = (const float*)d_in[17];
    const float* be2 = (const float*)d_in[18];
    const float* mu2 = (const float*)d_in[19];
    const float* va2 = (const float*)d_in[20];
    const int*   idxraw = (const int*)d_in[21];
    float* out = (float*)d_out;

    constexpr int SW = 36;
    int smem1 = 2 * (128 + 128) * SW * 4;   // 73728 B
    int smem2 = 2 * (128 + 64)  * SW * 4;   // 55296 B
    cudaFuncSetAttribute(k_tc<128,128,2,4,1>,
                         cudaFuncAttributeMaxDynamicSharedMemorySize, smem1);
    cudaFuncSetAttribute(k_tc<128,64,4,2,2>,
                         cudaFuncAttributeMaxDynamicSharedMemorySize, smem2);

    k_idx<<<(SQ*UU + 255)/256, 256>>>(idxraw);
    k_qkv<<<SQ, LT>>>(x, Wq, bq, Wk, bk, Wv, bv);
    k_sampleM<<<LH, SQ>>>();
    k_topk<<<LH/4, 128>>>();
    k_attn<<<LH, 256>>>();
    k_ctx<<<LH, SQ>>>();
    k_out1<<<SQ, LT>>>(x, Wo, bo, g1, be1, mu1, va1);
    k_tc<128,128,2,4,1><<<dim3(NH/128, SQ/128), 256, smem1>>>(
        W1, b1, nullptr, KF, NH, nullptr, nullptr, nullptr, nullptr);
    k_tc<128,64,4,2,2><<<dim3(KF/64, SQ/128), 256, smem2>>>(
        W2, b2, out, NH, KF, g2, be2, mu2, va2);
    (void)in_sizes; (void)n_in; (void)out_size;
}